// round 7
// baseline (speedup 1.0000x reference)
#include <cuda_runtime.h>
#include <math.h>

#define DD      64
#define TRI     2080          // 64*65/2
#define NT      96            // 3 warps; 72 compute lanes (36 tiles x 2 slices)
#define CHUNK   16            // nodes per smem chunk
#define RSTRIDE 68            // padded row stride (floats)

#define MAX_M  100000
#define MAX_G  1024

__device__ float g_imp[MAX_M];      // imp, overwritten with sqrt(e) by k_softmax
__device__ float g_invd[MAX_G];     // 1/denom per graph
__device__ int   g_start[MAX_G + 1];

// ---------------------------------------------------------------------------
// Segment boundaries from sorted batch, inline int64/int32 dtype sniff.
// ---------------------------------------------------------------------------
__global__ void k_bounds(const void* __restrict__ batch, int M, int G) {
    __shared__ int s_is64;
    const int* b32 = (const int*)batch;
    const long long* b64 = (const long long*)batch;

    if (threadIdx.x == 0) {
        int anynz = 0;
#pragma unroll
        for (int k = 1; k < 32; ++k) {
            long long pos = ((long long)k * M) / 32;
            int idx = (int)(pos | 1);           // odd word index
            if (idx < M) anynz |= (b32[idx] != 0);
        }
        s_is64 = (anynz == 0) ? 1 : 0;
    }
    __syncthreads();
    int is64 = s_is64;

    int m = blockIdx.x * blockDim.x + threadIdx.x;
    if (m >= M) return;
    int b  = is64 ? (int)b64[m] : b32[m];
    int pb;
    if (m == 0) pb = -1;
    else        pb = is64 ? (int)b64[m - 1] : b32[m - 1];
    if (b  < 0) b  = 0; if (b  >= G) b  = G - 1;
    if (pb < -1) pb = -1; if (pb >= G) pb = G - 1;
    for (int g = pb + 1; g <= b; ++g) g_start[g] = m;
    if (m == M - 1) {
        for (int g = b + 1; g <= G; ++g) g_start[g] = M;
    }
}

// ---------------------------------------------------------------------------
// imp[m] = dot(x[m], w) + bias. One warp per node, chip-wide parallel.
// ---------------------------------------------------------------------------
__global__ void k_imp(const float* __restrict__ x, const float* __restrict__ w,
                      const float* __restrict__ bias, int M) {
    int gwarp = (blockIdx.x * blockDim.x + threadIdx.x) >> 5;
    int lane  = threadIdx.x & 31;
    if (gwarp >= M) return;
    const float* xr = x + (size_t)gwarp * DD;
    float v = xr[lane] * __ldg(w + lane) + xr[lane + 32] * __ldg(w + lane + 32);
#pragma unroll
    for (int o = 16; o; o >>= 1) v += __shfl_xor_sync(0xFFFFFFFFu, v, o);
    if (lane == 0) g_imp[gwarp] = v + __ldg(bias);
}

// ---------------------------------------------------------------------------
// Per-graph softmax stats: g_imp[s..s+n) := sqrt(e_k); g_invd[g] := 1/denom.
// ---------------------------------------------------------------------------
__global__ __launch_bounds__(128)
void k_softmax(int G) {
    __shared__ float sred[4];
    __shared__ float sbr;
    int g    = blockIdx.x;
    int tid  = threadIdx.x;
    int lane = tid & 31;
    int wid  = tid >> 5;
    int s    = g_start[g];
    int n    = g_start[g + 1] - s;

    float mx = -3.402823466e38f;
    for (int i = tid; i < n; i += 128) mx = fmaxf(mx, g_imp[s + i]);
#pragma unroll
    for (int o = 16; o; o >>= 1) mx = fmaxf(mx, __shfl_xor_sync(0xFFFFFFFFu, mx, o));
    if (lane == 0) sred[wid] = mx;
    __syncthreads();
    if (tid == 0)
        sbr = fmaxf(fmaxf(sred[0], sred[1]), fmaxf(sred[2], sred[3]));
    __syncthreads();
    mx = sbr;

    float sum = 0.f;
    for (int i = tid; i < n; i += 128) {
        float sq = expf(0.5f * (g_imp[s + i] - mx));
        sum += sq * sq;
        g_imp[s + i] = sq;                 // same-thread RW, no race
    }
#pragma unroll
    for (int o = 16; o; o >>= 1) sum += __shfl_xor_sync(0xFFFFFFFFu, sum, o);
    if (lane == 0) sred[wid] = sum;
    __syncthreads();
    if (tid == 0) {
        float t = sred[0] + sred[1] + sred[2] + sred[3];
        g_invd[g] = (n > 0) ? (1.0f / t) : 0.0f;
    }
}

// ---------------------------------------------------------------------------
// Pure weighted SYRK per graph + triu writeout.
// smem rows = sqrt(e_k)*x_k, so acc = sum e_k x x^T with pure FFMA.
// Double-buffered chunks, one barrier per chunk.
// ---------------------------------------------------------------------------
__global__ __launch_bounds__(NT)
void k_syrk(const float* __restrict__ x, float* __restrict__ out) {
    __shared__ float sz[2][CHUNK * RSTRIDE];

    int g   = blockIdx.x;
    int tid = threadIdx.x;
    int s   = g_start[g];
    int n   = g_start[g + 1] - s;
    float inv_denom = g_invd[g];

    bool isComp = (tid < 72);
    int  tile   = tid >> 1;
    int  slice  = tid & 1;
    int  ti = 0, tmp = tile;
#pragma unroll
    for (int r = 0; r < 8; ++r) {
        int rl = 8 - r;
        if (ti == r && tmp >= rl) { tmp -= rl; ti = r + 1; }
    }
    int tj = ti + tmp;

    float acc[8][8];
#pragma unroll
    for (int i = 0; i < 8; ++i)
#pragma unroll
        for (int j = 0; j < 8; ++j) acc[i][j] = 0.f;

    int nch = (n + CHUNK - 1) / CHUNK;

    // loader: rows scaled by precomputed sqrt(e) (g_imp), zero-filled tail
#define LOAD_CHUNK(cidx, buf)                                                  \
    do {                                                                       \
        int _base = (cidx) * CHUNK;                                            \
        for (int q = tid; q < CHUNK * 16; q += NT) {                           \
            int _row = q >> 4, _c4 = q & 15;                                   \
            float4 _v = make_float4(0.f, 0.f, 0.f, 0.f);                       \
            int _node = _base + _row;                                          \
            if (_node < n) {                                                   \
                float _sq = g_imp[s + _node];                                  \
                _v = __ldg((const float4*)(x + ((size_t)(s + _node) << 6)) + _c4); \
                _v.x *= _sq; _v.y *= _sq; _v.z *= _sq; _v.w *= _sq;            \
            }                                                                  \
            *(float4*)&sz[buf][_row * RSTRIDE + _c4 * 4] = _v;                 \
        }                                                                      \
    } while (0)

    if (nch > 0) LOAD_CHUNK(0, 0);

    for (int c = 0; c < nch; ++c) {
        __syncthreads();                 // chunk c visible; buf (c+1)&1 free
        if (c + 1 < nch) LOAD_CHUNK(c + 1, (c + 1) & 1);

        if (isComp) {
            const float* zb = sz[c & 1];
#pragma unroll
            for (int k = 0; k < CHUNK / 2; ++k) {
                int kk = 2 * k + slice;
                const float* row = zb + kk * RSTRIDE;
                float4 a0 = *(const float4*)&row[ti * 8];
                float4 a1 = *(const float4*)&row[ti * 8 + 4];
                float4 b0 = *(const float4*)&row[tj * 8];
                float4 b1 = *(const float4*)&row[tj * 8 + 4];
                float a[8] = { a0.x, a0.y, a0.z, a0.w, a1.x, a1.y, a1.z, a1.w };
                float b[8] = { b0.x, b0.y, b0.z, b0.w, b1.x, b1.y, b1.z, b1.w };
#pragma unroll
                for (int i = 0; i < 8; ++i)
#pragma unroll
                    for (int j = 0; j < 8; ++j)
                        acc[i][j] += a[i] * b[j];
            }
        }
    }

    // slice combine (pairs are adjacent lanes in the same warp) + writeout
    if (isComp) {
        unsigned msk = (tid < 64) ? 0xFFFFFFFFu : 0x000000FFu;
#pragma unroll
        for (int i = 0; i < 8; ++i)
#pragma unroll
            for (int j = 0; j < 8; ++j)
                acc[i][j] += __shfl_xor_sync(msk, acc[i][j], 1);

        if (slice == 0) {
            float* og = out + (size_t)g * TRI;
            if (ti == tj) {
#pragma unroll
                for (int i = 0; i < 8; ++i) {
                    int gi = ti * 8 + i;
                    int base = gi * DD - (gi * (gi - 1)) / 2 - gi;
#pragma unroll
                    for (int j = 0; j < 8; ++j) {
                        int gj = tj * 8 + j;
                        if (gj >= gi) og[base + gj] = acc[i][j] * inv_denom;
                    }
                }
            } else {
#pragma unroll
                for (int i = 0; i < 8; ++i) {
                    int gi = ti * 8 + i;
                    int base = gi * DD - (gi * (gi - 1)) / 2 - gi;
#pragma unroll
                    for (int j = 0; j < 8; ++j)
                        og[base + tj * 8 + j] = acc[i][j] * inv_denom;
                }
            }
        }
    }
#undef LOAD_CHUNK
}

// ---------------------------------------------------------------------------
// Launch. Inputs identified BY SIZE (order-invariant):
//   att_b: size 1; att_w: size 64; batch: size*64 == size of x; edge: leftover.
// ---------------------------------------------------------------------------
extern "C" void kernel_launch(void* const* d_in, const int* in_sizes, int n_in,
                              void* d_out, int out_size) {
    int ib = -1, iw = -1, ibatch = -1, ix = -1;
    for (int i = 0; i < n_in; ++i) {
        if (in_sizes[i] == 1)       ib = i;
        else if (in_sizes[i] == DD) iw = i;
    }
    for (int i = 0; i < n_in && ibatch < 0; ++i) {
        if (i == ib || i == iw) continue;
        for (int j = 0; j < n_in; ++j) {
            if (j == i || j == ib || j == iw) continue;
            if ((long long)in_sizes[i] * DD == (long long)in_sizes[j]) {
                ibatch = i; ix = j; break;
            }
        }
    }
    if (ib < 0 || iw < 0 || ibatch < 0 || ix < 0) {  // fallback: reference order
        ix = 0; iw = 1; ib = 2; ibatch = 3;
    }

    const float* x    = (const float*)d_in[ix];
    const float* w    = (const float*)d_in[iw];
    const float* bias = (const float*)d_in[ib];
    const void*  batch = d_in[ibatch];

    int M = in_sizes[ix] / DD;
    int G = out_size / TRI;
    float* out = (float*)d_out;

    k_bounds<<<(M + 255) / 256, 256>>>(batch, M, G);
    k_imp<<<(M * 32 + 255) / 256, 256>>>(x, w, bias, M);
    k_softmax<<<G, 128>>>(G);
    k_syrk<<<G, NT>>>(x, out);
}

// round 9
// speedup vs baseline: 1.6736x; 1.6736x over previous
#include <cuda_runtime.h>
#include <math.h>

#define DD     64
#define TRI    2080          // 64*65/2
#define NT     128           // threads per SYRK block
#define CHUNK  16            // nodes per smem chunk
#define RSTRIDE 68           // padded row stride (floats)

#define MAX_M  100000
#define MAX_G  1024

// scratch (no allocations allowed)
__device__ float g_imp[MAX_M];
__device__ int   g_start[MAX_G + 1];

// ---------------------------------------------------------------------------
// Kernel 0: segment boundaries from sorted batch, inline int64/int32 sniff.
// int64 batch (values < 2^31): every odd 32-bit word is 0.
// int32 sorted batch: sampled odd words across the array are > 0.
// ---------------------------------------------------------------------------
__global__ void k_bounds(const void* __restrict__ batch, int M, int G) {
    __shared__ int s_is64;
    const int* b32 = (const int*)batch;
    const long long* b64 = (const long long*)batch;

    if (threadIdx.x == 0) {
        int anynz = 0;
#pragma unroll
        for (int k = 1; k < 32; ++k) {
            long long pos = ((long long)k * M) / 32;
            int idx = (int)(pos | 1);           // odd word index
            if (idx < M) anynz |= (b32[idx] != 0);
        }
        s_is64 = (anynz == 0) ? 1 : 0;
    }
    __syncthreads();
    int is64 = s_is64;

    int m = blockIdx.x * blockDim.x + threadIdx.x;
    if (m >= M) return;
    int b  = is64 ? (int)b64[m] : b32[m];
    int pb;
    if (m == 0) pb = -1;
    else        pb = is64 ? (int)b64[m - 1] : b32[m - 1];
    if (b  < 0) b  = 0; if (b  >= G) b  = G - 1;
    if (pb < -1) pb = -1; if (pb >= G) pb = G - 1;
    for (int g = pb + 1; g <= b; ++g) g_start[g] = m;
    if (m == M - 1) {
        for (int g = b + 1; g <= G; ++g) g_start[g] = M;
    }
}

// ---------------------------------------------------------------------------
// Kernel 1: imp[m] = dot(x[m], w) + bias. One warp per node, fully coalesced.
// (verbatim from round 3 — measured good)
// ---------------------------------------------------------------------------
__global__ void k_imp(const float* __restrict__ x, const float* __restrict__ w,
                      const float* __restrict__ bias, int M) {
    int gwarp = (blockIdx.x * blockDim.x + threadIdx.x) >> 5;
    int lane  = threadIdx.x & 31;
    if (gwarp >= M) return;
    const float* xr = x + (size_t)gwarp * DD;
    float v = xr[lane] * __ldg(w + lane) + xr[lane + 32] * __ldg(w + lane + 32);
#pragma unroll
    for (int o = 16; o; o >>= 1) v += __shfl_xor_sync(0xFFFFFFFFu, v, o);
    if (lane == 0) g_imp[gwarp] = v + __ldg(bias);
}

// ---------------------------------------------------------------------------
// Kernel 2: per-graph softmax + weighted SYRK, triu writeout.
// One block per graph. 36 upper 8x8 tiles x 2 k-slices = 72 compute threads.
// (verbatim from round 3 — measured 34.2us, best k_syrk so far)
// ---------------------------------------------------------------------------
__global__ __launch_bounds__(NT)
void k_syrk(const float* __restrict__ x, float* __restrict__ out, int G) {
    __shared__ float sz[CHUNK * RSTRIDE];
    __shared__ float se[CHUNK];
    __shared__ float sred[NT / 32];
    __shared__ float sbr[2];

    int g   = blockIdx.x;
    int tid = threadIdx.x;
    int s   = g_start[g];
    int n   = g_start[g + 1] - s;

    // ---- segment max ----
    float mx = -3.402823466e38f;
    for (int i = tid; i < n; i += NT) mx = fmaxf(mx, g_imp[s + i]);
#pragma unroll
    for (int o = 16; o; o >>= 1) mx = fmaxf(mx, __shfl_xor_sync(0xFFFFFFFFu, mx, o));
    if ((tid & 31) == 0) sred[tid >> 5] = mx;
    __syncthreads();
    if (tid == 0) {
        float m2 = sred[0];
#pragma unroll
        for (int i = 1; i < NT / 32; ++i) m2 = fmaxf(m2, sred[i]);
        sbr[0] = m2;
    }
    __syncthreads();
    mx = sbr[0];

    // ---- segment denom ----
    float sum = 0.f;
    for (int i = tid; i < n; i += NT) sum += expf(g_imp[s + i] - mx);
#pragma unroll
    for (int o = 16; o; o >>= 1) sum += __shfl_xor_sync(0xFFFFFFFFu, sum, o);
    if ((tid & 31) == 0) sred[tid >> 5] = sum;
    __syncthreads();
    if (tid == 0) {
        float t = 0.f;
#pragma unroll
        for (int i = 0; i < NT / 32; ++i) t += sred[i];
        sbr[1] = (n > 0) ? (1.0f / t) : 0.0f;
    }
    __syncthreads();
    float inv_denom = sbr[1];

    // ---- tile mapping: tid<72, tile = tid>>1 in [0,36), slice = tid&1 ----
    bool isComp = (tid < 72);
    int  tile   = tid >> 1;
    int  slice  = tid & 1;
    int  ti = 0, tmp = tile;
#pragma unroll
    for (int r = 0; r < 8; ++r) {
        int rl = 8 - r;
        if (ti == r && tmp >= rl) { tmp -= rl; ti = r + 1; }
    }
    int tj = ti + tmp;

    float acc[8][8];
#pragma unroll
    for (int i = 0; i < 8; ++i)
#pragma unroll
        for (int j = 0; j < 8; ++j) acc[i][j] = 0.f;

    // ---- main loop over node chunks (single-buffered — measured best) ----
    for (int c0 = 0; c0 < n; c0 += CHUNK) {
        __syncthreads();   // previous chunk's compute done before overwrite
#pragma unroll
        for (int q = tid; q < CHUNK * 16; q += NT) {
            int row = q >> 4, c4 = q & 15;
            float4 v = make_float4(0.f, 0.f, 0.f, 0.f);
            int node = c0 + row;
            if (node < n)
                v = __ldg((const float4*)(x + ((size_t)(s + node) << 6)) + c4);
            *(float4*)&sz[row * RSTRIDE + c4 * 4] = v;
        }
        if (tid < CHUNK) {
            int node = c0 + tid;
            se[tid] = (node < n) ? expf(g_imp[s + node] - mx) : 0.0f;
        }
        __syncthreads();

        if (isComp) {
#pragma unroll 2
            for (int k = 0; k < CHUNK / 2; ++k) {
                int kk = 2 * k + slice;
                const float* row = &sz[kk * RSTRIDE];
                float ek = se[kk];
                float4 a0 = *(const float4*)&row[ti * 8];
                float4 a1 = *(const float4*)&row[ti * 8 + 4];
                float4 b0 = *(const float4*)&row[tj * 8];
                float4 b1 = *(const float4*)&row[tj * 8 + 4];
                float a[8] = { a0.x * ek, a0.y * ek, a0.z * ek, a0.w * ek,
                               a1.x * ek, a1.y * ek, a1.z * ek, a1.w * ek };
                float b[8] = { b0.x, b0.y, b0.z, b0.w, b1.x, b1.y, b1.z, b1.w };
#pragma unroll
                for (int i = 0; i < 8; ++i)
#pragma unroll
                    for (int j = 0; j < 8; ++j)
                        acc[i][j] += a[i] * b[j];
            }
        }
    }

    // ---- combine slices (pairs are adjacent lanes in same warp) + writeout ----
    if (isComp) {
        unsigned msk = (tid < 64) ? 0xFFFFFFFFu : 0x000000FFu;
#pragma unroll
        for (int i = 0; i < 8; ++i)
#pragma unroll
            for (int j = 0; j < 8; ++j)
                acc[i][j] += __shfl_xor_sync(msk, acc[i][j], 1);

        if (slice == 0) {
            float* og = out + (size_t)g * TRI;
#pragma unroll
            for (int i = 0; i < 8; ++i) {
                int gi = ti * 8 + i;
                int base = gi * DD - (gi * (gi - 1)) / 2 - gi;  // + gj gives triu index
#pragma unroll
                for (int j = 0; j < 8; ++j) {
                    int gj = tj * 8 + j;
                    if (gj >= gi) og[base + gj] = acc[i][j] * inv_denom;
                }
            }
        }
    }
}

// ---------------------------------------------------------------------------
// Launch. Inputs identified BY SIZE (order-invariant):
//   att_b: size 1; att_w: size 64; batch: size*64 == size of x; edge: leftover.
// ---------------------------------------------------------------------------
extern "C" void kernel_launch(void* const* d_in, const int* in_sizes, int n_in,
                              void* d_out, int out_size) {
    int ib = -1, iw = -1, ibatch = -1, ix = -1;
    for (int i = 0; i < n_in; ++i) {
        if (in_sizes[i] == 1)       ib = i;
        else if (in_sizes[i] == DD) iw = i;
    }
    for (int i = 0; i < n_in && ibatch < 0; ++i) {
        if (i == ib || i == iw) continue;
        for (int j = 0; j < n_in; ++j) {
            if (j == i || j == ib || j == iw) continue;
            if ((long long)in_sizes[i] * DD == (long long)in_sizes[j]) {
                ibatch = i; ix = j; break;
            }
        }
    }
    if (ib < 0 || iw < 0 || ibatch < 0 || ix < 0) {  // fallback: reference order
        ix = 0; iw = 1; ib = 2; ibatch = 3;
    }

    const float* x    = (const float*)d_in[ix];
    const float* w    = (const float*)d_in[iw];
    const float* bias = (const float*)d_in[ib];
    const void*  batch = d_in[ibatch];

    int M = in_sizes[ix] / DD;
    int G = out_size / TRI;
    float* out = (float*)d_out;

    k_bounds<<<(M + 255) / 256, 256>>>(batch, M, G);
    k_imp<<<(M * 32 + 255) / 256, 256>>>(x, w, bias, M);
    k_syrk<<<G, NT>>>(x, out, G);
}

// round 10
// speedup vs baseline: 1.7377x; 1.0383x over previous
#include <cuda_runtime.h>
#include <math.h>

#define DD     64
#define TRI    2080          // 64*65/2
#define NT     128           // threads per SYRK block
#define CHUNK  16            // nodes per smem chunk
#define RSTRIDE 68           // padded row stride (floats)

#define MAX_M  100000
#define MAX_G  1024

// scratch (no allocations allowed)
__device__ float g_imp[MAX_M];
__device__ int   g_start[MAX_G + 1];

// ---------------------------------------------------------------------------
// Kernel 0: segment boundaries from sorted batch, per-thread dtype sniff.
// int64 batch (values < 2^31): every odd 32-bit word is 0.
// int32 sorted batch: odd words in the upper half of the array are > 0.
// All threads sample the SAME 8 odd words -> L2/L1 broadcast, no serialization.
// ---------------------------------------------------------------------------
__global__ void k_bounds(const void* __restrict__ batch, int M, int G) {
    const int* b32 = (const int*)batch;
    const long long* b64 = (const long long*)batch;

    int anynz = 0;
#pragma unroll
    for (int k = 0; k < 8; ++k) {
        // spread across upper half: M/2, 9M/16, ..., 15M/16 — forced odd, in-bounds
        int idx = (int)(((long long)M * (8 + k)) / 16) | 1;
        if (idx >= M) idx = (M - 1) | 1;
        if (idx >= M) idx -= 2;
        if (idx >= 1) anynz |= (__ldg(b32 + idx) != 0);
    }
    int is64 = (anynz == 0) ? 1 : 0;

    int m = blockIdx.x * blockDim.x + threadIdx.x;
    if (m >= M) return;
    int b  = is64 ? (int)b64[m] : b32[m];
    int pb;
    if (m == 0) pb = -1;
    else        pb = is64 ? (int)b64[m - 1] : b32[m - 1];
    if (b  < 0) b  = 0; if (b  >= G) b  = G - 1;
    if (pb < -1) pb = -1; if (pb >= G) pb = G - 1;
    for (int g = pb + 1; g <= b; ++g) g_start[g] = m;
    if (m == M - 1) {
        for (int g = b + 1; g <= G; ++g) g_start[g] = M;
    }
}

// ---------------------------------------------------------------------------
// Kernel 1: imp[m] = dot(x[m], w) + bias. One warp per node, fully coalesced.
// (verbatim — measured good)
// ---------------------------------------------------------------------------
__global__ void k_imp(const float* __restrict__ x, const float* __restrict__ w,
                      const float* __restrict__ bias, int M) {
    int gwarp = (blockIdx.x * blockDim.x + threadIdx.x) >> 5;
    int lane  = threadIdx.x & 31;
    if (gwarp >= M) return;
    const float* xr = x + (size_t)gwarp * DD;
    float v = xr[lane] * __ldg(w + lane) + xr[lane + 32] * __ldg(w + lane + 32);
#pragma unroll
    for (int o = 16; o; o >>= 1) v += __shfl_xor_sync(0xFFFFFFFFu, v, o);
    if (lane == 0) g_imp[gwarp] = v + __ldg(bias);
}

// ---------------------------------------------------------------------------
// Kernel 2: per-graph softmax + weighted SYRK, triu writeout.
// One block per graph. 36 upper 8x8 tiles x 2 k-slices = 72 compute threads.
// (verbatim — measured 34.2us, best k_syrk so far)
// ---------------------------------------------------------------------------
__global__ __launch_bounds__(NT)
void k_syrk(const float* __restrict__ x, float* __restrict__ out, int G) {
    __shared__ float sz[CHUNK * RSTRIDE];
    __shared__ float se[CHUNK];
    __shared__ float sred[NT / 32];
    __shared__ float sbr[2];

    int g   = blockIdx.x;
    int tid = threadIdx.x;
    int s   = g_start[g];
    int n   = g_start[g + 1] - s;

    // ---- segment max ----
    float mx = -3.402823466e38f;
    for (int i = tid; i < n; i += NT) mx = fmaxf(mx, g_imp[s + i]);
#pragma unroll
    for (int o = 16; o; o >>= 1) mx = fmaxf(mx, __shfl_xor_sync(0xFFFFFFFFu, mx, o));
    if ((tid & 31) == 0) sred[tid >> 5] = mx;
    __syncthreads();
    if (tid == 0) {
        float m2 = sred[0];
#pragma unroll
        for (int i = 1; i < NT / 32; ++i) m2 = fmaxf(m2, sred[i]);
        sbr[0] = m2;
    }
    __syncthreads();
    mx = sbr[0];

    // ---- segment denom ----
    float sum = 0.f;
    for (int i = tid; i < n; i += NT) sum += expf(g_imp[s + i] - mx);
#pragma unroll
    for (int o = 16; o; o >>= 1) sum += __shfl_xor_sync(0xFFFFFFFFu, sum, o);
    if ((tid & 31) == 0) sred[tid >> 5] = sum;
    __syncthreads();
    if (tid == 0) {
        float t = 0.f;
#pragma unroll
        for (int i = 0; i < NT / 32; ++i) t += sred[i];
        sbr[1] = (n > 0) ? (1.0f / t) : 0.0f;
    }
    __syncthreads();
    float inv_denom = sbr[1];

    // ---- tile mapping: tid<72, tile = tid>>1 in [0,36), slice = tid&1 ----
    bool isComp = (tid < 72);
    int  tile   = tid >> 1;
    int  slice  = tid & 1;
    int  ti = 0, tmp = tile;
#pragma unroll
    for (int r = 0; r < 8; ++r) {
        int rl = 8 - r;
        if (ti == r && tmp >= rl) { tmp -= rl; ti = r + 1; }
    }
    int tj = ti + tmp;

    float acc[8][8];
#pragma unroll
    for (int i = 0; i < 8; ++i)
#pragma unroll
        for (int j = 0; j < 8; ++j) acc[i][j] = 0.f;

    // ---- main loop over node chunks (single-buffered — measured best) ----
    for (int c0 = 0; c0 < n; c0 += CHUNK) {
        __syncthreads();   // previous chunk's compute done before overwrite
#pragma unroll
        for (int q = tid; q < CHUNK * 16; q += NT) {
            int row = q >> 4, c4 = q & 15;
            float4 v = make_float4(0.f, 0.f, 0.f, 0.f);
            int node = c0 + row;
            if (node < n)
                v = __ldg((const float4*)(x + ((size_t)(s + node) << 6)) + c4);
            *(float4*)&sz[row * RSTRIDE + c4 * 4] = v;
        }
        if (tid < CHUNK) {
            int node = c0 + tid;
            se[tid] = (node < n) ? expf(g_imp[s + node] - mx) : 0.0f;
        }
        __syncthreads();

        if (isComp) {
#pragma unroll 2
            for (int k = 0; k < CHUNK / 2; ++k) {
                int kk = 2 * k + slice;
                const float* row = &sz[kk * RSTRIDE];
                float ek = se[kk];
                float4 a0 = *(const float4*)&row[ti * 8];
                float4 a1 = *(const float4*)&row[ti * 8 + 4];
                float4 b0 = *(const float4*)&row[tj * 8];
                float4 b1 = *(const float4*)&row[tj * 8 + 4];
                float a[8] = { a0.x * ek, a0.y * ek, a0.z * ek, a0.w * ek,
                               a1.x * ek, a1.y * ek, a1.z * ek, a1.w * ek };
                float b[8] = { b0.x, b0.y, b0.z, b0.w, b1.x, b1.y, b1.z, b1.w };
#pragma unroll
                for (int i = 0; i < 8; ++i)
#pragma unroll
                    for (int j = 0; j < 8; ++j)
                        acc[i][j] += a[i] * b[j];
            }
        }
    }

    // ---- combine slices (pairs are adjacent lanes in same warp) + writeout ----
    if (isComp) {
        unsigned msk = (tid < 64) ? 0xFFFFFFFFu : 0x000000FFu;
#pragma unroll
        for (int i = 0; i < 8; ++i)
#pragma unroll
            for (int j = 0; j < 8; ++j)
                acc[i][j] += __shfl_xor_sync(msk, acc[i][j], 1);

        if (slice == 0) {
            float* og = out + (size_t)g * TRI;
#pragma unroll
            for (int i = 0; i < 8; ++i) {
                int gi = ti * 8 + i;
                int base = gi * DD - (gi * (gi - 1)) / 2 - gi;  // + gj gives triu index
#pragma unroll
                for (int j = 0; j < 8; ++j) {
                    int gj = tj * 8 + j;
                    if (gj >= gi) og[base + gj] = acc[i][j] * inv_denom;
                }
            }
        }
    }
}

// ---------------------------------------------------------------------------
// Launch. Inputs identified BY SIZE (order-invariant):
//   att_b: size 1; att_w: size 64; batch: size*64 == size of x; edge: leftover.
// ---------------------------------------------------------------------------
extern "C" void kernel_launch(void* const* d_in, const int* in_sizes, int n_in,
                              void* d_out, int out_size) {
    int ib = -1, iw = -1, ibatch = -1, ix = -1;
    for (int i = 0; i < n_in; ++i) {
        if (in_sizes[i] == 1)       ib = i;
        else if (in_sizes[i] == DD) iw = i;
    }
    for (int i = 0; i < n_in && ibatch < 0; ++i) {
        if (i == ib || i == iw) continue;
        for (int j = 0; j < n_in; ++j) {
            if (j == i || j == ib || j == iw) continue;
            if ((long long)in_sizes[i] * DD == (long long)in_sizes[j]) {
                ibatch = i; ix = j; break;
            }
        }
    }
    if (ib < 0 || iw < 0 || ibatch < 0 || ix < 0) {  // fallback: reference order
        ix = 0; iw = 1; ib = 2; ibatch = 3;
    }

    const float* x    = (const float*)d_in[ix];
    const float* w    = (const float*)d_in[iw];
    const float* bias = (const float*)d_in[ib];
    const void*  batch = d_in[ibatch];

    int M = in_sizes[ix] / DD;
    int G = out_size / TRI;
    float* out = (float*)d_out;

    k_bounds<<<(M + 255) / 256, 256>>>(batch, M, G);
    k_imp<<<(M * 32 + 255) / 256, 256>>>(x, w, bias, M);
    k_syrk<<<G, NT>>>(x, out, G);
}